// round 12
// baseline (speedup 1.0000x reference)
#include <cuda_runtime.h>
#include <math.h>
#include <stdint.h>

#define NROWS   262144
#define NCTA    2048
#define ROWS_PER_CTA (NROWS / NCTA)     // 128
#define TILE_R  16                      // rows per pipeline stage (8 KB)
#define STAGES  4
#define NT      (ROWS_PER_CTA / TILE_R) // 8 tiles per CTA

// Unified per-block 16x16 matrices: g_M4[j*64 + d*4 + q] = M[j][d][4q..4q+3]
__device__ float4 g_M4[8 * 16 * 4];

__global__ void bdla_prep(const float* __restrict__ W,
                          const float* __restrict__ s,
                          const float* __restrict__ U,
                          const float* __restrict__ V) {
    float* gm = (float*)g_M4;
    for (int e = threadIdx.x + blockIdx.x * blockDim.x; e < 8 * 16 * 16;
         e += blockDim.x * gridDim.x) {
        int j = e >> 8;
        int rem = e & 255;
        int d = rem >> 4;
        int o = rem & 15;
        float val;
        if (j == 0 || j == 3 || j == 6) {            // dense: y = x @ W^T
            int k = j / 3;
            val = W[k * 256 + o * 16 + d];
        } else if (j == 1 || j == 4 || j == 7) {     // diagonal
            int k = (j - 1) / 3;
            val = (d == o) ? s[k * 16 + d] : 0.0f;
        } else {                                     // lowrank: (V U^T)[d][o]
            int k = (j - 2) / 3;
            float acc = 0.0f;
            #pragma unroll
            for (int r = 0; r < 4; ++r)
                acc += V[k * 64 + d * 4 + r] * U[k * 64 + o * 4 + r];
            val = acc;
        }
        gm[j * 256 + d * 16 + o] = val;
    }
}

__device__ __forceinline__ void cpa16(uint32_t dst, const float4* src) {
    asm volatile("cp.async.cg.shared.global [%0], [%1], 16;"
                 :: "r"(dst), "l"(src));
}
__device__ __forceinline__ void cpa_commit() {
    asm volatile("cp.async.commit_group;");
}
__device__ __forceinline__ void cpa_wait3() {
    asm volatile("cp.async.wait_group 3;");
}

__global__ void __launch_bounds__(128, 6)
bdla_main(const float4* __restrict__ x, float4* __restrict__ y) {
    __shared__ float4 sx[STAGES][TILE_R * 32];   // 4 x 8 KB = 32 KB

    const int tid  = threadIdx.x;
    const int lane = tid & 31;
    const int wid  = tid >> 5;                   // 0..3
    const int j    = lane >> 2;                  // block id
    const int q    = lane & 3;                   // output quad
    const unsigned ctaRow0 = blockIdx.x * ROWS_PER_CTA;

    // 64 weight registers per lane (R6-proven layout).
    float4 w[16];
    {
        const float4* Mp = g_M4 + (j << 6) + q;
        #pragma unroll
        for (int d = 0; d < 16; ++d) w[d] = Mp[d * 4];
    }

    const float4* gsrc0 = x + (size_t)ctaRow0 * 32;
    const uint32_t sbase = (uint32_t)__cvta_generic_to_shared(&sx[0][0]);

    // Prologue: prefetch tiles 0..STAGES-2 (one commit group per tile).
    #pragma unroll
    for (int t = 0; t < STAGES - 1; ++t) {
        const uint32_t dst0 = sbase + (uint32_t)(t * TILE_R * 512);
        const float4* src0 = gsrc0 + t * TILE_R * 32;
        #pragma unroll
        for (int i = 0; i < 4; ++i)
            cpa16(dst0 + (tid + 128 * i) * 16u, src0 + tid + 128 * i);
        cpa_commit();
    }

    // Per-warp invariant bases (keeps live address regs minimal).
    const uint32_t sread0 = sbase + (uint32_t)((wid * 32 + j * 4) * 16);
    float4* ywbase = y + (size_t)(ctaRow0 + wid) * 32 + lane;

    int stage = 0, pstage = STAGES - 1;
    #pragma unroll 1
    for (int t = 0; t < NT; ++t) {
        // Issue tile t+STAGES-1; empty commit groups keep wait_group aligned.
        const int tp = t + STAGES - 1;
        if (tp < NT) {
            const uint32_t dst0 = sbase + (uint32_t)(pstage * TILE_R * 512);
            const float4* src0 = gsrc0 + tp * TILE_R * 32;
            #pragma unroll
            for (int i = 0; i < 4; ++i)
                cpa16(dst0 + (tid + 128 * i) * 16u, src0 + tid + 128 * i);
        }
        cpa_commit();

        cpa_wait3();              // tile t's group complete (<=3 pending)
        __syncthreads();          // visible to all warps

        // Single base address for this warp's reads of tile t; all row/sb
        // offsets are compile-time immediates on LDS.
        const uint32_t tbase = sread0 + (uint32_t)(stage * TILE_R * 512);

        #pragma unroll
        for (int k = 0; k < 4; ++k) {
            float y0 = 0.f, y1 = 0.f, y2 = 0.f, y3 = 0.f;
            #pragma unroll
            for (int sb = 0; sb < 4; ++sb) {
                float4 a;
                asm volatile("ld.shared.v4.f32 {%0,%1,%2,%3}, [%4];"
                             : "=f"(a.x), "=f"(a.y), "=f"(a.z), "=f"(a.w)
                             : "r"(tbase + (uint32_t)((k * 4 * 512) + sb * 16)));
                const float4 w0 = w[4 * sb + 0];
                const float4 w1 = w[4 * sb + 1];
                const float4 w2 = w[4 * sb + 2];
                const float4 w3 = w[4 * sb + 3];
                y0 = fmaf(a.x, w0.x, y0); y1 = fmaf(a.x, w0.y, y1);
                y2 = fmaf(a.x, w0.z, y2); y3 = fmaf(a.x, w0.w, y3);
                y0 = fmaf(a.y, w1.x, y0); y1 = fmaf(a.y, w1.y, y1);
                y2 = fmaf(a.y, w1.z, y2); y3 = fmaf(a.y, w1.w, y3);
                y0 = fmaf(a.z, w2.x, y0); y1 = fmaf(a.z, w2.y, y1);
                y2 = fmaf(a.z, w2.z, y2); y3 = fmaf(a.z, w2.w, y3);
                y0 = fmaf(a.w, w3.x, y0); y1 = fmaf(a.w, w3.y, y1);
                y2 = fmaf(a.w, w3.z, y2); y3 = fmaf(a.w, w3.w, y3);
            }

            // Row L2 norm across all 32 lanes.
            float ss = y0 * y0;
            ss = fmaf(y1, y1, ss); ss = fmaf(y2, y2, ss); ss = fmaf(y3, y3, ss);
            #pragma unroll
            for (int m = 16; m >= 1; m >>= 1)
                ss += __shfl_xor_sync(0xffffffffu, ss, m);
            const float inv = rsqrtf(ss);

            // Store: warp-invariant base + immediate row offset.
            ywbase[(size_t)(t * TILE_R + 4 * k) * 32] =
                make_float4(y0 * inv, y1 * inv, y2 * inv, y3 * inv);
        }

        __syncthreads();          // stage reused by the issue at t+1

        stage  = (stage  == STAGES - 1) ? 0 : stage + 1;
        pstage = (pstage == STAGES - 1) ? 0 : pstage + 1;
    }
}

extern "C" void kernel_launch(void* const* d_in, const int* in_sizes, int n_in,
                              void* d_out, int out_size) {
    const float* x = (const float*)d_in[0];
    const float* W = (const float*)d_in[1];
    const float* s = (const float*)d_in[2];
    const float* U = (const float*)d_in[3];
    const float* V = (const float*)d_in[4];
    float* out = (float*)d_out;

    bdla_prep<<<8, 256>>>(W, s, U, V);
    bdla_main<<<NCTA, 128>>>((const float4*)x, (float4*)out);
}

// round 13
// speedup vs baseline: 1.4015x; 1.4015x over previous
#include <cuda_runtime.h>
#include <math.h>
#include <stdint.h>

#define NROWS   262144
#define NCTA    2048
#define ROWS_PER_CTA (NROWS / NCTA)     // 128
#define TILE_R  16                      // rows per pipeline stage (8 KB)
#define STAGES  4
#define NT      (ROWS_PER_CTA / TILE_R) // 8 tiles per CTA

__device__ __forceinline__ void cpa16(uint32_t dst, const float4* src) {
    asm volatile("cp.async.cg.shared.global [%0], [%1], 16;"
                 :: "r"(dst), "l"(src));
}
__device__ __forceinline__ void cpa_commit() {
    asm volatile("cp.async.commit_group;");
}
__device__ __forceinline__ void cpa_wait3() {
    asm volatile("cp.async.wait_group 3;");
}

__global__ void __launch_bounds__(128)
bdla_main(const float4* __restrict__ x, float4* __restrict__ y,
          const float* __restrict__ Wd, const float* __restrict__ s,
          const float* __restrict__ U, const float* __restrict__ V) {
    __shared__ float4 sx[STAGES][TILE_R * 32];   // 4 x 8 KB
    __shared__ float  swt[2048];                 // swt[j*256 + d*16 + ob]

    const int tid  = threadIdx.x;
    const int lane = tid & 31;
    const int wid  = tid >> 5;                   // 0..3
    const int j    = lane >> 2;                  // block id
    const int q    = lane & 3;                   // output quad
    const unsigned ctaRow0 = blockIdx.x * ROWS_PER_CTA;

    const float4* gsrc0 = x + (size_t)ctaRow0 * 32;
    const uint32_t sbase = (uint32_t)__cvta_generic_to_shared(&sx[0][0]);

    // Prologue: start DRAM traffic for tiles 0..2 first.
    #pragma unroll
    for (int t = 0; t < STAGES - 1; ++t) {
        const uint32_t dst0 = sbase + (uint32_t)(t * TILE_R * 512);
        const float4* src0 = gsrc0 + t * TILE_R * 32;
        #pragma unroll
        for (int i = 0; i < 4; ++i)
            cpa16(dst0 + (tid + 128 * i) * 16u, src0 + tid + 128 * i);
        cpa_commit();
    }

    // Build the unified per-block 16x16 matrices in smem, FULLY UNROLLED so
    // all parameter LDGs are independent and overlap (R11's serial-latency
    // mistake fixed). DENSE {0,3,6}: M[d][ob]=W[k][ob][d]; DIAG {1,4,7}:
    // diag(s); LR {2,5}: (V U^T)[d][ob].
    #pragma unroll
    for (int i = 0; i < 16; ++i) {
        const int e = tid + 128 * i;
        const int jj = e >> 8;
        const int rem = e & 255;
        const int d = rem >> 4;
        const int o = rem & 15;
        float val;
        if (jj == 0 || jj == 3 || jj == 6) {
            const int k = jj / 3;
            val = Wd[k * 256 + o * 16 + d];
        } else if (jj == 1 || jj == 4 || jj == 7) {
            const int k = (jj - 1) / 3;
            val = (d == o) ? s[k * 16 + d] : 0.0f;
        } else {
            const int k = (jj - 2) / 3;
            float acc = 0.0f;
            #pragma unroll
            for (int r = 0; r < 4; ++r)
                acc += V[k * 64 + d * 4 + r] * U[k * 64 + o * 4 + r];
            val = acc;
        }
        swt[e] = val;
    }
    __syncthreads();

    // 64 weight registers per lane (R6-proven): w[d] = M[j][d][4q..4q+3].
    float4 w[16];
    {
        const float4* Mp = (const float4*)&swt[j * 256 + q * 4];
        #pragma unroll
        for (int d = 0; d < 16; ++d) w[d] = Mp[d * 4];
    }
    // swt is read-only from here on; no extra sync needed.

    int stage = 0, pstage = STAGES - 1;
    #pragma unroll 1
    for (int t = 0; t < NT; ++t) {
        // Issue tile t+STAGES-1; empty commit groups keep wait_group aligned.
        const int tp = t + STAGES - 1;
        if (tp < NT) {
            const uint32_t dst0 = sbase + (uint32_t)(pstage * TILE_R * 512);
            const float4* src0 = gsrc0 + tp * TILE_R * 32;
            #pragma unroll
            for (int i = 0; i < 4; ++i)
                cpa16(dst0 + (tid + 128 * i) * 16u, src0 + tid + 128 * i);
        }
        cpa_commit();

        cpa_wait3();              // tile t's group complete (<=3 pending)
        __syncthreads();          // visible to all warps

        const float4* tile = &sx[stage][0];

        // Each warp computes 4 rows of the 16-row tile.
        #pragma unroll
        for (int k = 0; k < 4; ++k) {
            const int rit = wid + 4 * k;
            const float4* rowp = tile + rit * 32 + j * 4;

            float y0 = 0.f, y1 = 0.f, y2 = 0.f, y3 = 0.f;
            #pragma unroll
            for (int sb = 0; sb < 4; ++sb) {
                const float4 a = rowp[sb];           // quad-broadcast LDS.128
                const float4 w0 = w[4 * sb + 0];
                const float4 w1 = w[4 * sb + 1];
                const float4 w2 = w[4 * sb + 2];
                const float4 w3 = w[4 * sb + 3];
                y0 = fmaf(a.x, w0.x, y0); y1 = fmaf(a.x, w0.y, y1);
                y2 = fmaf(a.x, w0.z, y2); y3 = fmaf(a.x, w0.w, y3);
                y0 = fmaf(a.y, w1.x, y0); y1 = fmaf(a.y, w1.y, y1);
                y2 = fmaf(a.y, w1.z, y2); y3 = fmaf(a.y, w1.w, y3);
                y0 = fmaf(a.z, w2.x, y0); y1 = fmaf(a.z, w2.y, y1);
                y2 = fmaf(a.z, w2.z, y2); y3 = fmaf(a.z, w2.w, y3);
                y0 = fmaf(a.w, w3.x, y0); y1 = fmaf(a.w, w3.y, y1);
                y2 = fmaf(a.w, w3.z, y2); y3 = fmaf(a.w, w3.w, y3);
            }

            // Row L2 norm across all 32 lanes.
            float ss = y0 * y0;
            ss = fmaf(y1, y1, ss); ss = fmaf(y2, y2, ss); ss = fmaf(y3, y3, ss);
            #pragma unroll
            for (int m = 16; m >= 1; m >>= 1)
                ss += __shfl_xor_sync(0xffffffffu, ss, m);
            const float inv = rsqrtf(ss);

            const unsigned grow = ctaRow0 + (unsigned)(t * TILE_R + rit);
            y[(size_t)grow * 32 + lane] =
                make_float4(y0 * inv, y1 * inv, y2 * inv, y3 * inv);
        }

        __syncthreads();          // stage reused by the issue at t+1

        stage  = (stage  == STAGES - 1) ? 0 : stage + 1;
        pstage = (pstage == STAGES - 1) ? 0 : pstage + 1;
    }
}

extern "C" void kernel_launch(void* const* d_in, const int* in_sizes, int n_in,
                              void* d_out, int out_size) {
    const float* x = (const float*)d_in[0];
    const float* W = (const float*)d_in[1];
    const float* s = (const float*)d_in[2];
    const float* U = (const float*)d_in[3];
    const float* V = (const float*)d_in[4];
    float* out = (float*)d_out;

    bdla_main<<<NCTA, 128>>>((const float4*)x, (float4*)out, W, s, U, V);
}